// round 14
// baseline (speedup 1.0000x reference)
#include <cuda_runtime.h>
#include <cuda_fp16.h>
#include <stdint.h>

// Problem constants
#define B     1024
#define S     2048
#define R1    20000
#define R2    40000
#define RTOT  (R1 + R2)            // 60000 concatenated reactions

#define MAIN_THREADS 512
#define NPART 4                    // uniform partitions over the concat stream
#define RPP   15000                // reactions per partition
#define EPT   30                   // entries per thread per partition (pad 15360)
#define PART_PAD (EPT * MAIN_THREADS)   // 15360
#define ONE_IDX 2048u              // y slot holding 1.0 (first-order rb target)
#define KPAD  2048u                // pad-entry key (discard slot)
#define SINK  2049                 // redirect target for non-closing stores
#define ACC_SLOTS 2052             // float2 slots (0..2047 real, 2048 pad, 2049 sink)
#define Y_SLOTS 2052
#define CHUNK 6                    // EPT / CHUNK = 5 double-buffered stages

// ---------------- static device scratch (no runtime allocation) ----------------
// g_counts starts zero (static zero-init); scan_kernel re-zeroes after reading.
__device__ int       g_counts[NPART][S];
__device__ int       g_cur[NPART][S];
// Key-grouped, transposed entry streams. u16x4 fields:
//   e = ra | rb<<16 | k<<32 | rid<<48   (first-order entries: rb = ONE_IDX)
__device__ uint64_t  g_et[NPART][PART_PAD];

__device__ __forceinline__ int transposeP(int pos) {
    return (pos % EPT) * MAIN_THREADS + pos / EPT;
}

__device__ __forceinline__ uint64_t pack_entry(unsigned ra, unsigned rb,
                                               unsigned k, unsigned rid) {
    return (uint64_t)ra | ((uint64_t)rb << 16) |
           ((uint64_t)k << 32) | ((uint64_t)rid << 48);
}

// ---------------- prep kernels ----------------

__global__ void hist_kernel(const int* __restrict__ inds_1p,
                            const int* __restrict__ inds_2p) {
    int g = blockIdx.x * blockDim.x + threadIdx.x;
    if (g < RTOT) {
        int part = g / RPP;
        int p = (g < R1) ? inds_1p[g] : inds_2p[g - R1];
        atomicAdd(&g_counts[part][p], 1);
    }
}

// One CTA per partition: exclusive scan over its 2048 bins -> running cursors.
// Re-zeroes its counts slice (restores the zero-at-entry invariant).
__global__ void scan_kernel() {
    __shared__ int buf[2][S];
    const int tid  = threadIdx.x;       // 1024 threads, 2 elems each
    const int part = blockIdx.x;

    int* cnt = g_counts[part];
    int* cur = g_cur[part];

    buf[0][tid]        = cnt[tid];
    buf[0][tid + 1024] = cnt[tid + 1024];
    cnt[tid]        = 0;
    cnt[tid + 1024] = 0;
    __syncthreads();

    int src = 0;
    for (int off = 1; off < S; off <<= 1) {
        int i0 = tid, i1 = tid + 1024;
        int v0 = buf[src][i0] + (i0 >= off ? buf[src][i0 - off] : 0);
        int v1 = buf[src][i1] + (i1 >= off ? buf[src][i1 - off] : 0);
        __syncthreads();
        buf[1 - src][i0] = v0;
        buf[1 - src][i1] = v1;
        __syncthreads();
        src ^= 1;
    }
    cur[tid]        = (tid == 0) ? 0 : buf[src][tid - 1];
    cur[tid + 1024] = buf[src][tid + 1023];
}

// Scatter entries into key-grouped transposed slots + write pad entries.
__global__ void scatter_pad_kernel(const int* __restrict__ inds_1r,
                                   const int* __restrict__ inds_1p,
                                   const int* __restrict__ inds_2r,
                                   const int* __restrict__ inds_2p) {
    int g = blockIdx.x * blockDim.x + threadIdx.x;
    if (g < RTOT) {
        int part = g / RPP;
        int rid  = g - part * RPP;          // index into staged rate buffer
        unsigned ra, rb, p;
        if (g < R1) {
            ra = (unsigned)inds_1r[g]; rb = ONE_IDX; p = (unsigned)inds_1p[g];
        } else {
            int j = g - R1;
            ra = (unsigned)inds_2r[2 * j]; rb = (unsigned)inds_2r[2 * j + 1];
            p = (unsigned)inds_2p[j];
        }
        int pos = atomicAdd(&g_cur[part][p], 1);
        g_et[part][transposeP(pos)] = pack_entry(ra, rb, p, (unsigned)rid);
    } else if (g < RTOT + NPART * (PART_PAD - RPP)) {
        int q    = g - RTOT;
        int part = q / (PART_PAD - RPP);
        int slot = RPP + q % (PART_PAD - RPP);
        // pad: 1.0 * 1.0 * rate[0] -> discard key KPAD
        g_et[part][transposeP(slot)] = pack_entry(ONE_IDX, ONE_IDX, KPAD, 0);
    }
}

// ---------------- main kernel ----------------
// TWO batch rows per CTA; y and rates packed __half2 {row0,row1}; fp32
// register run accumulation. Interior run closes are pure overwrite-STS.64
// into a per-partition scratch accumulator (valid: an interior key belongs
// to exactly one thread and one run per partition) — NO load, NO latency
// chain; non-closing entries store to a sink slot via SEL address. After
// each sweep, a trivial merge pass adds acc_part into acc_final and
// re-zeroes acc_part (fused into the next partition's rate staging).
// Slice-boundary runs go via spread SMEM atomics into acc_final (disjoint
// from sweep stores). Partitions are 4 x 15000 over the concatenated
// (rates_1st ++ rates_2nd) stream; the unified ONE-slot entry format makes
// cross-boundary partitions free.
//
// SMEM: y2h(8.2KB) + acc_final(16.4KB) + acc_part(16.4KB) + rbuf2h(60KB)
//     = 101KB -> 2 CTAs/SM.

#define SMEM_BYTES (Y_SLOTS * 4 + 2 * ACC_SLOTS * 4 * 2 + RPP * 4)

__device__ __forceinline__ void sweep2(
    const uint64_t* __restrict__ ep,      // g_et[part] + tid
    const __half2* __restrict__ y2h,
    const __half2* __restrict__ rbuf2h,
    float* __restrict__ accp,             // scratch (overwrite-STS target)
    unsigned& firstk, float& f0, float& f1, unsigned& fdone,
    unsigned& lastk, float& l0, float& l1)
{
    uint64_t buf0[CHUNK], buf1[CHUNK];
    #pragma unroll
    for (int u = 0; u < CHUNK; ++u)
        buf0[u] = ep[u * MAIN_THREADS];

    unsigned curk = 0;
    float a0 = 0.f, a1 = 0.f;
    unsigned first_done = 0;
    firstk = SINK; f0 = 0.f; f1 = 0.f;

    #pragma unroll
    for (int c = 0; c < EPT / CHUNK; ++c) {
        uint64_t* cur = (c & 1) ? buf1 : buf0;
        uint64_t* nxt = (c & 1) ? buf0 : buf1;
        if (c + 1 < EPT / CHUNK) {
            const uint64_t* np = ep + (c + 1) * CHUNK * MAIN_THREADS;
            #pragma unroll
            for (int u = 0; u < CHUNK; ++u)
                nxt[u] = np[u * MAIN_THREADS];
        }
        #pragma unroll
        for (int u = 0; u < CHUNK; ++u) {
            uint64_t e  = cur[u];
            unsigned lo = (unsigned)e;
            unsigned hi = (unsigned)(e >> 32);
            unsigned ra  = lo & 0xFFFFu;
            unsigned rb  = lo >> 16;
            unsigned k   = hi & 0xFFFFu;
            unsigned rid = hi >> 16;
            float2 fa = __half22float2(y2h[ra]);     // 1 random LDS.32
            float2 fb = __half22float2(y2h[rb]);     // random or broadcast
            float2 fr = __half22float2(rbuf2h[rid]); // 1 random LDS.32
            float v0 = fa.x * fb.x * fr.x;
            float v1 = fa.y * fb.y * fr.y;
            if (c == 0 && u == 0) {
                curk = k; a0 = v0; a1 = v1;      // prime first run
            } else {
                unsigned diff     = (k != curk) ? 1u : 0u;
                unsigned do_store = diff & first_done;
                // interior close: pure overwrite STS.64 (no load, no chain);
                // non-close: same store redirected to the sink slot.
                float* addr = do_store ? (accp + 2 * curk) : (accp + 2 * SINK);
                float2 t; t.x = a0; t.y = a1;
                *(float2*)addr = t;               // fire-and-forget STS.64
                unsigned cap = diff & (1u - first_done);
                firstk = cap ? curk : firstk;
                f0     = cap ? a0   : f0;
                f1     = cap ? a1   : f1;
                first_done |= diff;
                a0 = diff ? v0 : (a0 + v0);
                a1 = diff ? v1 : (a1 + v1);
                curk = k;
            }
        }
    }
    fdone = first_done;
    lastk = curk; l0 = a0; l1 = a1;
}

__global__ __launch_bounds__(MAIN_THREADS, 2)
void reaction_main_kernel(const float* __restrict__ y_in,
                          const float* __restrict__ rates_1st,
                          const float* __restrict__ rates_2nd,
                          float* __restrict__ y_out) {
    extern __shared__ char smraw[];
    __half2* y2h  = (__half2*)smraw;                              // [Y_SLOTS]
    float*   accf = (float*)(smraw + Y_SLOTS * 4);                // [2*ACC_SLOTS]
    float*   accp = (float*)(smraw + Y_SLOTS * 4 + 2 * ACC_SLOTS * 4);
    __half2* rbuf2h = (__half2*)(smraw + Y_SLOTS * 4 + 4 * ACC_SLOTS * 4); // [RPP]

    const int b0  = 2 * blockIdx.x;
    const int b1  = b0 + 1;
    const int tid = threadIdx.x;

    // Load two y rows -> packed half2; ONE slot; zero both accumulators.
    {
        const float4* s0 = (const float4*)(y_in + (size_t)b0 * S);
        const float4* s1 = (const float4*)(y_in + (size_t)b1 * S);
        float4 r0 = s0[tid], r1 = s1[tid];
        __half2 t[4];
        t[0] = __floats2half2_rn(r0.x, r1.x);
        t[1] = __floats2half2_rn(r0.y, r1.y);
        t[2] = __floats2half2_rn(r0.z, r1.z);
        t[3] = __floats2half2_rn(r0.w, r1.w);
        *(uint4*)(y2h + 4 * tid) = *(const uint4*)t;              // STS.128
        if (tid == 0)
            y2h[ONE_IDX] = __floats2half2_rn(1.f, 1.f);
        #pragma unroll
        for (int i = tid; i < 2 * ACC_SLOTS; i += MAIN_THREADS) {
            accf[i] = 0.f;
            accp[i] = 0.f;
        }
    }

    #pragma unroll 1
    for (int part = 0; part < NPART; ++part) {
        __syncthreads();   // prior sweep (rbuf reads, accp stores, atomics) done

        // ---- stage rates for this partition (+ merge previous accp) ----
        {
            const int gb = part * RPP;
            for (int i = tid; i < RPP / 4; i += MAIN_THREADS) {
                int g = gb + 4 * i;      // concat index; float4 never straddles R1
                const float4* s0;
                const float4* s1;
                if (g < R1) {
                    s0 = (const float4*)(rates_1st + (size_t)b0 * R1 + g);
                    s1 = (const float4*)(rates_1st + (size_t)b1 * R1 + g);
                } else {
                    s0 = (const float4*)(rates_2nd + (size_t)b0 * R2 + (g - R1));
                    s1 = (const float4*)(rates_2nd + (size_t)b1 * R2 + (g - R1));
                }
                float4 r0 = __ldcs(s0);
                float4 r1 = __ldcs(s1);
                __half2 t[4];
                t[0] = __floats2half2_rn(r0.x, r1.x);
                t[1] = __floats2half2_rn(r0.y, r1.y);
                t[2] = __floats2half2_rn(r0.z, r1.z);
                t[3] = __floats2half2_rn(r0.w, r1.w);
                *(uint4*)(rbuf2h + 4 * i) = *(const uint4*)t;     // STS.128
            }
            if (part > 0) {
                // merge previous partition's scratch into final; re-zero scratch
                #pragma unroll
                for (int s = tid; s < S; s += MAIN_THREADS) {
                    float2 v = *(float2*)(accp + 2 * s);
                    float2 z; z.x = 0.f; z.y = 0.f;
                    *(float2*)(accp + 2 * s) = z;
                    float2 a = *(float2*)(accf + 2 * s);
                    a.x += v.x; a.y += v.y;
                    *(float2*)(accf + 2 * s) = a;
                }
            }
        }
        __syncthreads();

        unsigned firstk, fdone, lastk;
        float f0, f1, l0, l1;
        sweep2(g_et[part] + tid, y2h, rbuf2h, accp,
               firstk, f0, f1, fdone, lastk, l0, l1);

        // boundary runs -> acc_final (disjoint array from sweep's accp stores,
        // so no barrier needed before these atomics)
        atomicAdd(&accf[2 * lastk],     l0);
        atomicAdd(&accf[2 * lastk + 1], l1);
        if (fdone) {
            atomicAdd(&accf[2 * firstk],     f0);
            atomicAdd(&accf[2 * firstk + 1], f1);
        }
    }
    __syncthreads();

    // final merge of last partition's scratch, then write out
    #pragma unroll
    for (int s = tid; s < S; s += MAIN_THREADS) {
        float2 v = *(float2*)(accp + 2 * s);
        float2 a = *(float2*)(accf + 2 * s);
        a.x += v.x; a.y += v.y;
        *(float2*)(accf + 2 * s) = a;
    }
    __syncthreads();

    #pragma unroll
    for (int i = tid; i < S; i += MAIN_THREADS) {
        float2 t = *(const float2*)(accf + 2 * i);
        y_out[(size_t)b0 * S + i] = t.x;
        y_out[(size_t)b1 * S + i] = t.y;
    }
}

// ---------------- launch ----------------

extern "C" void kernel_launch(void* const* d_in, const int* in_sizes, int n_in,
                              void* d_out, int out_size) {
    const float* y_in      = (const float*)d_in[0];
    const float* rates_1st = (const float*)d_in[1];
    const float* rates_2nd = (const float*)d_in[2];
    const int*   inds_1r   = (const int*)d_in[3];
    const int*   inds_1p   = (const int*)d_in[4];
    const int*   inds_2r   = (const int*)d_in[5];
    const int*   inds_2p   = (const int*)d_in[6];
    float*       y_out     = (float*)d_out;

    cudaFuncSetAttribute(reaction_main_kernel,
                         cudaFuncAttributeMaxDynamicSharedMemorySize,
                         SMEM_BYTES);

    // Entry-stream build (rebuilt every launch; deterministic).
    hist_kernel<<<(RTOT + 255) / 256, 256>>>(inds_1p, inds_2p);
    scan_kernel<<<NPART, 1024>>>();
    int scat_n = RTOT + NPART * (PART_PAD - RPP);
    scatter_pad_kernel<<<(scat_n + 255) / 256, 256>>>(inds_1r, inds_1p, inds_2r, inds_2p);

    // Main pass: one CTA per TWO batch rows
    reaction_main_kernel<<<B / 2, MAIN_THREADS, SMEM_BYTES>>>(
        y_in, rates_1st, rates_2nd, y_out);
}